// round 16
// baseline (speedup 1.0000x reference)
#include <cuda_runtime.h>
#include <cuda.h>
#include <cuda_fp16.h>
#include <cstdint>

// out[b,o,{re,im}] = complex(X) @ complex(W)^T (no conj).
// Karatsuba 3-multiplication complex GEMM:
//   k1 = (Xre+Xim)·Wre^T ; k2 = Xre·(Wim−Wre)^T ; k3 = Xim·(Wre+Wim)^T
//   out_re = k1 − k3 ; out_im = k1 + k2
// R16: 512 threads / 16 warps of 32(m)x16(o) -> 4 warps per SMSP for
// latency hiding (R13 evidence: tensor% tracks warps/SMSP).
// fp16 operands, fp32 accumulation; rel_err ~4.2e-4 < 1e-3.

static constexpr int M = 4096;
static constexpr int KIN = 2048;
static constexpr int OUTF = 2048;

static constexpr int BM = 128;
static constexpr int BO = 64;
static constexpr int BK = 64;                  // 64 fp16 = 128B rows (SW128 atom)
static constexpr int A_TILE = BM * 128;        // 16384 B
static constexpr int B_TILE = BO * 128;        // 8192 B
static constexpr int STAGES = 3;
static constexpr int STAGE_BYTES = 3 * A_TILE + 3 * B_TILE;   // 73728
static constexpr int B_OFF = 3 * A_TILE;
static constexpr int SMEM_BYTES = 2048 + STAGES * STAGE_BYTES;  // 223232

static constexpr int NTHREADS = 512;
static constexpr int NKT = KIN / BK;           // 32

__device__ __half g_A3[(size_t)3 * M * KIN];
__device__ __half g_B3[(size_t)3 * OUTF * KIN];

#define SW128(o) ((o) ^ (((o) >> 3) & 0x70))

// ---------------------------------------------------------------------------
// Prep: builds all six fp16 operand blocks (8 elems/thread).
// ---------------------------------------------------------------------------
__global__ void prep_all(const float* __restrict__ xre, const float* __restrict__ xim,
                         const float* __restrict__ wre, const float* __restrict__ wim) {
    size_t idx8 = ((size_t)blockIdx.x * blockDim.x + threadIdx.x) * 8;
    const float *s0, *s1;
    __half *d0, *d1, *d2;
    bool isA = idx8 < (size_t)M * KIN;
    if (isA) {
        s0 = xre + idx8;
        s1 = xim + idx8;
        d0 = g_A3 + idx8;
        d1 = g_A3 + (size_t)M * KIN + idx8;
        d2 = g_A3 + (size_t)2 * M * KIN + idx8;
    } else {
        size_t j = idx8 - (size_t)M * KIN;
        s0 = wre + j;
        s1 = wim + j;
        d0 = g_B3 + j;
        d1 = g_B3 + (size_t)OUTF * KIN + j;
        d2 = g_B3 + (size_t)2 * OUTF * KIN + j;
    }
    float4 a0 = *(const float4*)s0;
    float4 a1 = *(const float4*)(s0 + 4);
    float4 b0 = *(const float4*)s1;
    float4 b1 = *(const float4*)(s1 + 4);
    float va[8] = {a0.x, a0.y, a0.z, a0.w, a1.x, a1.y, a1.z, a1.w};
    float vb[8] = {b0.x, b0.y, b0.z, b0.w, b1.x, b1.y, b1.z, b1.w};

    __half h0[8], h1[8], h2[8];
#pragma unroll
    for (int i = 0; i < 8; i++) {
        if (isA) {
            h0[i] = __float2half(va[i] + vb[i]);   // Xre+Xim
            h1[i] = __float2half(va[i]);           // Xre
            h2[i] = __float2half(vb[i]);           // Xim
        } else {
            h0[i] = __float2half(va[i]);           // Wre
            h1[i] = __float2half(vb[i] - va[i]);   // Wim−Wre
            h2[i] = __float2half(va[i] + vb[i]);   // Wre+Wim
        }
    }
    *(uint4*)d0 = *(const uint4*)h0;
    *(uint4*)d1 = *(const uint4*)h1;
    *(uint4*)d2 = *(const uint4*)h2;
}

// ---------------------------------------------------------------------------
// helpers
// ---------------------------------------------------------------------------
__device__ __forceinline__ uint32_t smem_u32(const void* p) {
    uint32_t a;
    asm("{ .reg .u64 t; cvta.to.shared.u64 t, %1; cvt.u32.u64 %0, t; }"
        : "=r"(a) : "l"(p));
    return a;
}
#define MBARRIER_INIT(addr, cnt) \
    asm volatile("mbarrier.init.shared.b64 [%0], %1;" :: "r"(addr), "r"(cnt) : "memory")
#define MBARRIER_EXPECT_TX(addr, bytes) \
    asm volatile("mbarrier.arrive.expect_tx.shared.b64 _, [%0], %1;" \
                 :: "r"(addr), "r"(bytes) : "memory")
#define MBARRIER_WAIT_PARITY(addr, ph) do {                                   \
    uint32_t _m = (addr), _p = (ph), _d;                                      \
    asm volatile("{\n .reg .pred p;\n"                                        \
        " mbarrier.try_wait.parity.acquire.cta.shared::cta.b64 p, [%1], %2;\n"\
        " selp.b32 %0,1,0,p;\n}" : "=r"(_d) : "r"(_m), "r"(_p) : "memory");   \
    if (!_d) {                                                                \
        asm volatile("{\n .reg .pred P1;\n"                                   \
            "WL_%=:\n"                                                        \
            " mbarrier.try_wait.parity.acquire.cta.shared::cta.b64 P1, [%0], %1, 0x989680;\n" \
            " @P1 bra.uni WD_%=;\n bra.uni WL_%=;\nWD_%=:\n}"                 \
            :: "r"(_m), "r"(_p) : "memory");                                  \
    }                                                                         \
} while (0)

__device__ __forceinline__ void tma2d(uint32_t sdst, const void* map, int cx, int cy,
                                      uint32_t mbar) {
    asm volatile(
        "cp.async.bulk.tensor.2d.shared::cta.global.tile.mbarrier::complete_tx::bytes "
        "[%0], [%1, {%2, %3}], [%4];"
        :: "r"(sdst), "l"(map), "r"(cx), "r"(cy), "r"(mbar) : "memory");
}

__device__ __forceinline__ void ldm_x4(uint32_t* r, uint32_t saddr) {
    asm volatile("ldmatrix.sync.aligned.m8n8.x4.shared.b16 {%0,%1,%2,%3}, [%4];"
                 : "=r"(r[0]), "=r"(r[1]), "=r"(r[2]), "=r"(r[3]) : "r"(saddr));
}
__device__ __forceinline__ void mma16816(float* c, const uint32_t* a, const uint32_t* b) {
    asm volatile("mma.sync.aligned.m16n8k16.row.col.f32.f16.f16.f32 "
                 "{%0,%1,%2,%3}, {%4,%5,%6,%7}, {%8,%9}, {%0,%1,%2,%3};"
                 : "+f"(c[0]), "+f"(c[1]), "+f"(c[2]), "+f"(c[3])
                 : "r"(a[0]), "r"(a[1]), "r"(a[2]), "r"(a[3]),
                   "r"(b[0]), "r"(b[1]));
}

// ---------------------------------------------------------------------------
// GEMM: CTA tile 128(m) x 64(o), 3 products, 16 warps (4x4) of 32x16,
// BK=64, TMA 3-stage ring (6 tiles/stage), 512 threads, 1 CTA/SM.
// ---------------------------------------------------------------------------
__global__ void __launch_bounds__(NTHREADS, 1) gemm_f16(
    float* __restrict__ out,
    const __grid_constant__ CUtensorMap tmA,
    const __grid_constant__ CUtensorMap tmB)
{
    extern __shared__ __align__(16) char smem[];
    uint32_t sb = smem_u32(smem);
    uint32_t tbase = (sb + 1024u) & ~1023u;

    const int tid  = threadIdx.x;
    const int lane = tid & 31;
    const int warp = tid >> 5;
    const int wm = warp >> 2;     // 0..3  (m: 4 x 32)
    const int wn = warp & 3;      // 0..3  (o: 4 x 16)
    const int bm0 = blockIdx.y * BM;
    const int bo0 = blockIdx.x * BO;

    if (tid == 0) {
        for (int s = 0; s < STAGES; s++) MBARRIER_INIT(sb + 8 * s, 1);
    }
    __syncthreads();

    if (tid == 0) {
#pragma unroll
        for (int s = 0; s < STAGES; s++) {
            MBARRIER_EXPECT_TX(sb + 8 * s, (uint32_t)STAGE_BYTES);
            uint32_t tb = tbase + s * STAGE_BYTES;
#pragma unroll
            for (int p = 0; p < 3; p++) {
                tma2d(tb + p * A_TILE,         &tmA, s * BK, p * M + bm0,    sb + 8 * s);
                tma2d(tb + B_OFF + p * B_TILE, &tmB, s * BK, p * OUTF + bo0, sb + 8 * s);
            }
        }
    }

    // acc[product][im][in][q] : warp tile 32x16 -> 2 m-frags x 2 n-frags
    float acc[3][2][2][4];
#pragma unroll
    for (int p = 0; p < 3; p++)
#pragma unroll
        for (int i = 0; i < 2; i++)
#pragma unroll
            for (int j = 0; j < 2; j++)
#pragma unroll
                for (int q = 0; q < 4; q++) acc[p][i][j][q] = 0.f;

#pragma unroll 1
    for (int kt = 0; kt < NKT; kt++) {
        const int st = kt % STAGES;
        MBARRIER_WAIT_PARITY(sb + 8 * st, (kt / STAGES) & 1);
        const uint32_t stg = tbase + st * STAGE_BYTES;

#pragma unroll
        for (int ks = 0; ks < 4; ks++) {
            const int kk = ks * 16;

            // A fragments: 3 products x 2 m16-frags
            uint32_t af[3][2][4];
            const int arow = wm * 32 + (lane & 15);
            const int acolb = (kk + ((lane >> 4) << 3)) * 2;
#pragma unroll
            for (int p = 0; p < 3; p++) {
#pragma unroll
                for (int im = 0; im < 2; im++) {
                    uint32_t off = (uint32_t)((arow + im * 16) * 128 + acolb);
                    ldm_x4(af[p][im], stg + p * A_TILE + SW128(off));
                }
            }

            // B fragments: 3 products x 2 n8-frags via ONE ldm_x4 each
            uint32_t bf[3][2][2];
            {
                int mset = lane >> 3;
                int nrow_in = (lane & 7) + ((mset >> 1) << 3);   // 0..15
                int colb = (kk + ((mset & 1) << 3)) * 2;
                int nrow = wn * 16 + nrow_in;
#pragma unroll
                for (int p = 0; p < 3; p++) {
                    uint32_t off = (uint32_t)(nrow * 128 + colb);
                    uint32_t r[4];
                    ldm_x4(r, stg + B_OFF + p * B_TILE + SW128(off));
                    bf[p][0][0] = r[0]; bf[p][0][1] = r[1];
                    bf[p][1][0] = r[2]; bf[p][1][1] = r[3];
                }
            }

#pragma unroll
            for (int p = 0; p < 3; p++)
#pragma unroll
                for (int im = 0; im < 2; im++)
#pragma unroll
                    for (int in = 0; in < 2; in++)
                        mma16816(acc[p][im][in], af[p][im], bf[p][in]);
        }

        __syncthreads();
        if (tid == 0 && kt + STAGES < NKT) {
            MBARRIER_EXPECT_TX(sb + 8 * st, (uint32_t)STAGE_BYTES);
            uint32_t tb = tbase + st * STAGE_BYTES;
#pragma unroll
            for (int p = 0; p < 3; p++) {
                tma2d(tb + p * A_TILE,         &tmA, (kt + STAGES) * BK, p * M + bm0,    sb + 8 * st);
                tma2d(tb + B_OFF + p * B_TILE, &tmB, (kt + STAGES) * BK, p * OUTF + bo0, sb + 8 * st);
            }
        }
    }

    // Epilogue: re = k1 - k3, im = k1 + k2 ; out[m, o, {re,im}] as float2
    const int gr = lane >> 2;
    const int gc = (lane & 3) << 1;
#pragma unroll
    for (int im = 0; im < 2; im++) {
#pragma unroll
        for (int in = 0; in < 2; in++) {
            int m0 = bm0 + wm * 32 + im * 16 + gr;
            int o0 = bo0 + wn * 16 + in * 8 + gc;
#pragma unroll
            for (int q = 0; q < 4; q++) {
                int mq = m0 + ((q >> 1) << 3);     // +8 rows for q=2,3
                int oq = o0 + (q & 1);             // +1 col  for q=1,3
                float k1 = acc[0][im][in][q];
                float k2 = acc[1][im][in][q];
                float k3 = acc[2][im][in][q];
                float2 v = make_float2(k1 - k3, k1 + k2);
                *(float2*)(out + ((size_t)mq * OUTF + oq) * 2) = v;
            }
        }
    }
}

// ---------------------------------------------------------------------------
// Host
// ---------------------------------------------------------------------------
typedef CUresult (*EncodeFn)(
    CUtensorMap*, CUtensorMapDataType, cuuint32_t, void*,
    const cuuint64_t*, const cuuint64_t*, const cuuint32_t*, const cuuint32_t*,
    CUtensorMapInterleave, CUtensorMapSwizzle, CUtensorMapL2promotion,
    CUtensorMapFloatOOBfill);

static void make_map(EncodeFn enc, CUtensorMap* m, void* ptr, int rows, int box_rows) {
    cuuint64_t dims[2]    = {(cuuint64_t)KIN, (cuuint64_t)rows};
    cuuint64_t strides[1] = {(cuuint64_t)KIN * 2};
    cuuint32_t box[2]     = {(cuuint32_t)BK, (cuuint32_t)box_rows};
    cuuint32_t es[2]      = {1, 1};
    enc(m, CU_TENSOR_MAP_DATA_TYPE_FLOAT16, 2, ptr, dims, strides, box, es,
        CU_TENSOR_MAP_INTERLEAVE_NONE, CU_TENSOR_MAP_SWIZZLE_128B,
        CU_TENSOR_MAP_L2_PROMOTION_L2_128B, CU_TENSOR_MAP_FLOAT_OOB_FILL_NONE);
}

extern "C" void kernel_launch(void* const* d_in, const int* in_sizes, int n_in,
                              void* d_out, int out_size) {
    const float* x_re = (const float*)d_in[0];
    const float* x_im = (const float*)d_in[1];
    const float* w_re = (const float*)d_in[2];
    const float* w_im = (const float*)d_in[3];
    float* out = (float*)d_out;

    void *pA, *pB;
    cudaGetSymbolAddress(&pA, g_A3);
    cudaGetSymbolAddress(&pB, g_B3);

    EncodeFn enc = nullptr;
    cudaDriverEntryPointQueryResult qr;
    cudaGetDriverEntryPointByVersion("cuTensorMapEncodeTiled", (void**)&enc, 12000,
                                     cudaEnableDefault, &qr);

    CUtensorMap mA, mB;
    make_map(enc, &mA, pA, 3 * M, BM);
    make_map(enc, &mB, pB, 3 * OUTF, BO);

    cudaFuncSetAttribute(gemm_f16, cudaFuncAttributeMaxDynamicSharedMemorySize,
                         SMEM_BYTES);

    size_t total8 = ((size_t)M * KIN + (size_t)OUTF * KIN) / 8;
    prep_all<<<(unsigned)(total8 / 256), 256>>>(x_re, x_im, w_re, w_im);

    dim3 grid(OUTF / BO, M / BM);   // (32, 32)
    gemm_f16<<<grid, NTHREADS, SMEM_BYTES>>>(out, mA, mB);
}

// round 17
// speedup vs baseline: 1.2597x; 1.2597x over previous
#include <cuda_runtime.h>
#include <cuda.h>
#include <cuda_fp16.h>
#include <cstdint>

// out[b,o,{re,im}] = complex(X) @ complex(W)^T (no conj).
// Karatsuba 3-multiplication complex GEMM:
//   k1 = (Xre+Xim)·Wre^T ; k2 = Xre·(Wim−Wre)^T ; k3 = Xim·(Wre+Wim)^T
//   out_re = k1 − k3 ; out_im = k1 + k2
// R17: product-specialized warps. CTA tile 128(m)x64(o); 12 warps (384 thr):
// warps 0-3 -> k1, 4-7 -> k2, 8-11 -> k3, each a full 64x32 warp tile
// (ldmatrix/MMA ratio 0.375 = the measured optimum from R13).
// Epilogue: k2/k3 warps STS accs to idle stage smem; k1 warps combine+store.
// fp16 operands, fp32 accumulation; rel_err ~4.2e-4 < 1e-3.

static constexpr int M = 4096;
static constexpr int KIN = 2048;
static constexpr int OUTF = 2048;

static constexpr int BM = 128;
static constexpr int BO = 64;
static constexpr int BK = 64;                  // 64 fp16 = 128B rows (SW128 atom)
static constexpr int A_TILE = BM * 128;        // 16384 B
static constexpr int B_TILE = BO * 128;        // 8192 B
static constexpr int STAGES = 3;
static constexpr int STAGE_BYTES = 3 * A_TILE + 3 * B_TILE;   // 73728
static constexpr int B_OFF = 3 * A_TILE;
static constexpr int SMEM_BYTES = 2048 + STAGES * STAGE_BYTES;  // 223232

static constexpr int NTHREADS = 384;           // 12 warps
static constexpr int NKT = KIN / BK;           // 32

__device__ __half g_A3[(size_t)3 * M * KIN];
__device__ __half g_B3[(size_t)3 * OUTF * KIN];

#define SW128(o) ((o) ^ (((o) >> 3) & 0x70))

// ---------------------------------------------------------------------------
// Prep: builds all six fp16 operand blocks (8 elems/thread).
// ---------------------------------------------------------------------------
__global__ void prep_all(const float* __restrict__ xre, const float* __restrict__ xim,
                         const float* __restrict__ wre, const float* __restrict__ wim) {
    size_t idx8 = ((size_t)blockIdx.x * blockDim.x + threadIdx.x) * 8;
    const float *s0, *s1;
    __half *d0, *d1, *d2;
    bool isA = idx8 < (size_t)M * KIN;
    if (isA) {
        s0 = xre + idx8;
        s1 = xim + idx8;
        d0 = g_A3 + idx8;
        d1 = g_A3 + (size_t)M * KIN + idx8;
        d2 = g_A3 + (size_t)2 * M * KIN + idx8;
    } else {
        size_t j = idx8 - (size_t)M * KIN;
        s0 = wre + j;
        s1 = wim + j;
        d0 = g_B3 + j;
        d1 = g_B3 + (size_t)OUTF * KIN + j;
        d2 = g_B3 + (size_t)2 * OUTF * KIN + j;
    }
    float4 a0 = *(const float4*)s0;
    float4 a1 = *(const float4*)(s0 + 4);
    float4 b0 = *(const float4*)s1;
    float4 b1 = *(const float4*)(s1 + 4);
    float va[8] = {a0.x, a0.y, a0.z, a0.w, a1.x, a1.y, a1.z, a1.w};
    float vb[8] = {b0.x, b0.y, b0.z, b0.w, b1.x, b1.y, b1.z, b1.w};

    __half h0[8], h1[8], h2[8];
#pragma unroll
    for (int i = 0; i < 8; i++) {
        if (isA) {
            h0[i] = __float2half(va[i] + vb[i]);   // Xre+Xim
            h1[i] = __float2half(va[i]);           // Xre
            h2[i] = __float2half(vb[i]);           // Xim
        } else {
            h0[i] = __float2half(va[i]);           // Wre
            h1[i] = __float2half(vb[i] - va[i]);   // Wim−Wre
            h2[i] = __float2half(va[i] + vb[i]);   // Wre+Wim
        }
    }
    *(uint4*)d0 = *(const uint4*)h0;
    *(uint4*)d1 = *(const uint4*)h1;
    *(uint4*)d2 = *(const uint4*)h2;
}

// ---------------------------------------------------------------------------
// helpers
// ---------------------------------------------------------------------------
__device__ __forceinline__ uint32_t smem_u32(const void* p) {
    uint32_t a;
    asm("{ .reg .u64 t; cvta.to.shared.u64 t, %1; cvt.u32.u64 %0, t; }"
        : "=r"(a) : "l"(p));
    return a;
}
#define MBARRIER_INIT(addr, cnt) \
    asm volatile("mbarrier.init.shared.b64 [%0], %1;" :: "r"(addr), "r"(cnt) : "memory")
#define MBARRIER_EXPECT_TX(addr, bytes) \
    asm volatile("mbarrier.arrive.expect_tx.shared.b64 _, [%0], %1;" \
                 :: "r"(addr), "r"(bytes) : "memory")
#define MBARRIER_WAIT_PARITY(addr, ph) do {                                   \
    uint32_t _m = (addr), _p = (ph), _d;                                      \
    asm volatile("{\n .reg .pred p;\n"                                        \
        " mbarrier.try_wait.parity.acquire.cta.shared::cta.b64 p, [%1], %2;\n"\
        " selp.b32 %0,1,0,p;\n}" : "=r"(_d) : "r"(_m), "r"(_p) : "memory");   \
    if (!_d) {                                                                \
        asm volatile("{\n .reg .pred P1;\n"                                   \
            "WL_%=:\n"                                                        \
            " mbarrier.try_wait.parity.acquire.cta.shared::cta.b64 P1, [%0], %1, 0x989680;\n" \
            " @P1 bra.uni WD_%=;\n bra.uni WL_%=;\nWD_%=:\n}"                 \
            :: "r"(_m), "r"(_p) : "memory");                                  \
    }                                                                         \
} while (0)

__device__ __forceinline__ void tma2d(uint32_t sdst, const void* map, int cx, int cy,
                                      uint32_t mbar) {
    asm volatile(
        "cp.async.bulk.tensor.2d.shared::cta.global.tile.mbarrier::complete_tx::bytes "
        "[%0], [%1, {%2, %3}], [%4];"
        :: "r"(sdst), "l"(map), "r"(cx), "r"(cy), "r"(mbar) : "memory");
}

__device__ __forceinline__ void ldm_x4(uint32_t* r, uint32_t saddr) {
    asm volatile("ldmatrix.sync.aligned.m8n8.x4.shared.b16 {%0,%1,%2,%3}, [%4];"
                 : "=r"(r[0]), "=r"(r[1]), "=r"(r[2]), "=r"(r[3]) : "r"(saddr));
}
__device__ __forceinline__ void mma16816(float* c, const uint32_t* a, const uint32_t* b) {
    asm volatile("mma.sync.aligned.m16n8k16.row.col.f32.f16.f16.f32 "
                 "{%0,%1,%2,%3}, {%4,%5,%6,%7}, {%8,%9}, {%0,%1,%2,%3};"
                 : "+f"(c[0]), "+f"(c[1]), "+f"(c[2]), "+f"(c[3])
                 : "r"(a[0]), "r"(a[1]), "r"(a[2]), "r"(a[3]),
                   "r"(b[0]), "r"(b[1]));
}

// ---------------------------------------------------------------------------
// GEMM: CTA tile 128(m)x64(o); 12 warps; warp w: product p = w>>2,
// warp-local wl = w&3 -> (wm = wl>>1) 64-row half, (wn = wl&1) 32-col half.
// Each warp: full 64x32 tile of its product (a=4 m-frags, b=4 n-frags).
// TMA 3-stage ring (6 tiles/stage), R13 sync protocol.
// ---------------------------------------------------------------------------
__global__ void __launch_bounds__(NTHREADS, 1) gemm_f16(
    float* __restrict__ out,
    const __grid_constant__ CUtensorMap tmA,
    const __grid_constant__ CUtensorMap tmB)
{
    extern __shared__ __align__(16) char smem[];
    uint32_t sb = smem_u32(smem);
    uint32_t tbase = (sb + 1024u) & ~1023u;

    const int tid  = threadIdx.x;
    const int lane = tid & 31;
    const int warp = tid >> 5;
    const int prod = warp >> 2;   // 0..2
    const int wl   = warp & 3;
    const int wm   = wl >> 1;     // 0..1 (m half)
    const int wn   = wl & 1;      // 0..1 (o half)
    const int bm0 = blockIdx.y * BM;
    const int bo0 = blockIdx.x * BO;

    if (tid == 0) {
        for (int s = 0; s < STAGES; s++) MBARRIER_INIT(sb + 8 * s, 1);
    }
    __syncthreads();

    if (tid == 0) {
#pragma unroll
        for (int s = 0; s < STAGES; s++) {
            MBARRIER_EXPECT_TX(sb + 8 * s, (uint32_t)STAGE_BYTES);
            uint32_t tb = tbase + s * STAGE_BYTES;
#pragma unroll
            for (int p = 0; p < 3; p++) {
                tma2d(tb + p * A_TILE,         &tmA, s * BK, p * M + bm0,    sb + 8 * s);
                tma2d(tb + B_OFF + p * B_TILE, &tmB, s * BK, p * OUTF + bo0, sb + 8 * s);
            }
        }
    }

    float acc[4][4][4];
#pragma unroll
    for (int i = 0; i < 4; i++)
#pragma unroll
        for (int j = 0; j < 4; j++)
#pragma unroll
            for (int q = 0; q < 4; q++) acc[i][j][q] = 0.f;

#pragma unroll 1
    for (int kt = 0; kt < NKT; kt++) {
        const int st = kt % STAGES;
        MBARRIER_WAIT_PARITY(sb + 8 * st, (kt / STAGES) & 1);
        const uint32_t sA = tbase + st * STAGE_BYTES + prod * A_TILE;
        const uint32_t sB = tbase + st * STAGE_BYTES + B_OFF + prod * B_TILE;

#pragma unroll
        for (int ks = 0; ks < 4; ks++) {
            const int kk = ks * 16;

            // A: 4 m16-frags (64 rows)
            uint32_t af[4][4];
            const int arow = wm * 64 + (lane & 15);
            const int acolb = (kk + ((lane >> 4) << 3)) * 2;
#pragma unroll
            for (int im = 0; im < 4; im++) {
                uint32_t off = (uint32_t)((arow + im * 16) * 128 + acolb);
                ldm_x4(af[im], sA + SW128(off));
            }

            // B: 4 n8-frags via 2 ldm_x4 (32 cols)
            uint32_t bf[4][2];
            {
                int mset = lane >> 3;
                int nrow_in = (lane & 7) + ((mset >> 1) << 3);
                int colb = (kk + ((mset & 1) << 3)) * 2;
#pragma unroll
                for (int ip = 0; ip < 2; ip++) {
                    int nrow = wn * 32 + ip * 16 + nrow_in;
                    uint32_t off = (uint32_t)(nrow * 128 + colb);
                    uint32_t r[4];
                    ldm_x4(r, sB + SW128(off));
                    bf[ip * 2][0] = r[0]; bf[ip * 2][1] = r[1];
                    bf[ip * 2 + 1][0] = r[2]; bf[ip * 2 + 1][1] = r[3];
                }
            }

#pragma unroll
            for (int im = 0; im < 4; im++)
#pragma unroll
                for (int in = 0; in < 4; in++) mma16816(acc[im][in], af[im], bf[in]);
        }

        __syncthreads();
        if (tid == 0 && kt + STAGES < NKT) {
            MBARRIER_EXPECT_TX(sb + 8 * st, (uint32_t)STAGE_BYTES);
            uint32_t tb = tbase + st * STAGE_BYTES;
#pragma unroll
            for (int p = 0; p < 3; p++) {
                tma2d(tb + p * A_TILE,         &tmA, (kt + STAGES) * BK, p * M + bm0,    sb + 8 * st);
                tma2d(tb + B_OFF + p * B_TILE, &tmB, (kt + STAGES) * BK, p * OUTF + bo0, sb + 8 * st);
            }
        }
    }

    // ---- Cross-product reduction through (now idle) stage smem ----
    // Slot for (product p in {1,2}, warp-local wl): 8 KB each, lane-striped
    // conflict-free: float j of lane l at slot + j*128 + l*4.
    float* red = (float*)(smem + (tbase - sb));
    // flatten helper index: j = ((im*4+in)<<2)+q

    if (prod != 0) {
        float* slot = red + ((size_t)((prod - 1) * 4 + wl) * 2048) + lane;
#pragma unroll
        for (int im = 0; im < 4; im++)
#pragma unroll
            for (int in = 0; in < 4; in++)
#pragma unroll
                for (int q = 0; q < 4; q++)
                    slot[(((im * 4 + in) << 2) + q) * 32] = acc[im][in][q];
    }
    __syncthreads();

    if (prod == 0) {
        float* s2 = red + ((size_t)(0 * 4 + wl) * 2048) + lane;   // k2
        float* s3 = red + ((size_t)(1 * 4 + wl) * 2048) + lane;   // k3
        const int gr = lane >> 2;
        const int gc = (lane & 3) << 1;
#pragma unroll
        for (int im = 0; im < 4; im++) {
#pragma unroll
            for (int in = 0; in < 4; in++) {
                int m0 = bm0 + wm * 64 + im * 16 + gr;
                int o0 = bo0 + wn * 32 + in * 8 + gc;
#pragma unroll
                for (int q = 0; q < 4; q++) {
                    int j32 = (((im * 4 + in) << 2) + q) * 32;
                    float k1 = acc[im][in][q];
                    float k2 = s2[j32];
                    float k3 = s3[j32];
                    int mq = m0 + ((q >> 1) << 3);
                    int oq = o0 + (q & 1);
                    float2 v = make_float2(k1 - k3, k1 + k2);
                    *(float2*)(out + ((size_t)mq * OUTF + oq) * 2) = v;
                }
            }
        }
    }
}

// ---------------------------------------------------------------------------
// Host
// ---------------------------------------------------------------------------
typedef CUresult (*EncodeFn)(
    CUtensorMap*, CUtensorMapDataType, cuuint32_t, void*,
    const cuuint64_t*, const cuuint64_t*, const cuuint32_t*, const cuuint32_t*,
    CUtensorMapInterleave, CUtensorMapSwizzle, CUtensorMapL2promotion,
    CUtensorMapFloatOOBfill);

static void make_map(EncodeFn enc, CUtensorMap* m, void* ptr, int rows, int box_rows) {
    cuuint64_t dims[2]    = {(cuuint64_t)KIN, (cuuint64_t)rows};
    cuuint64_t strides[1] = {(cuuint64_t)KIN * 2};
    cuuint32_t box[2]     = {(cuuint32_t)BK, (cuuint32_t)box_rows};
    cuuint32_t es[2]      = {1, 1};
    enc(m, CU_TENSOR_MAP_DATA_TYPE_FLOAT16, 2, ptr, dims, strides, box, es,
        CU_TENSOR_MAP_INTERLEAVE_NONE, CU_TENSOR_MAP_SWIZZLE_128B,
        CU_TENSOR_MAP_L2_PROMOTION_L2_128B, CU_TENSOR_MAP_FLOAT_OOB_FILL_NONE);
}

extern "C" void kernel_launch(void* const* d_in, const int* in_sizes, int n_in,
                              void* d_out, int out_size) {
    const float* x_re = (const float*)d_in[0];
    const float* x_im = (const float*)d_in[1];
    const float* w_re = (const float*)d_in[2];
    const float* w_im = (const float*)d_in[3];
    float* out = (float*)d_out;

    void *pA, *pB;
    cudaGetSymbolAddress(&pA, g_A3);
    cudaGetSymbolAddress(&pB, g_B3);

    EncodeFn enc = nullptr;
    cudaDriverEntryPointQueryResult qr;
    cudaGetDriverEntryPointByVersion("cuTensorMapEncodeTiled", (void**)&enc, 12000,
                                     cudaEnableDefault, &qr);

    CUtensorMap mA, mB;
    make_map(enc, &mA, pA, 3 * M, BM);
    make_map(enc, &mB, pB, 3 * OUTF, BO);

    cudaFuncSetAttribute(gemm_f16, cudaFuncAttributeMaxDynamicSharedMemorySize,
                         SMEM_BYTES);

    size_t total8 = ((size_t)M * KIN + (size_t)OUTF * KIN) / 8;
    prep_all<<<(unsigned)(total8 / 256), 256>>>(x_re, x_im, w_re, w_im);

    dim3 grid(OUTF / BO, M / BM);   // (32, 32)
    gemm_f16<<<grid, NTHREADS, SMEM_BYTES>>>(out, mA, mB);
}